// round 15
// baseline (speedup 1.0000x reference)
#include <cuda_runtime.h>
#include <cuda_fp16.h>

typedef unsigned long long u64;

// ---------------- cp.async helpers ----------------
__device__ __forceinline__ unsigned smem_u32(const void* p) {
    return (unsigned)__cvta_generic_to_shared(p);
}
__device__ __forceinline__ void cp16(unsigned dst, const void* src) {
    asm volatile("cp.async.cg.shared.global [%0], [%1], 16;"
                 :: "r"(dst), "l"(src));
}
__device__ __forceinline__ void cp_commit() {
    asm volatile("cp.async.commit_group;");
}
template<int N>
__device__ __forceinline__ void cp_wait() {
    asm volatile("cp.async.wait_group %0;" :: "n"(N));
}

// ---------------- mma.sync helpers (baseline PTX, no 'a' features) ----------------
__device__ __forceinline__ void ldm4(unsigned r[4], unsigned addr) {
    asm volatile("ldmatrix.sync.aligned.m8n8.x4.shared.b16 {%0,%1,%2,%3}, [%4];"
                 : "=r"(r[0]), "=r"(r[1]), "=r"(r[2]), "=r"(r[3]) : "r"(addr));
}
// fp16 inputs, fp32 accumulate (main term)
__device__ __forceinline__ void mma16816(float c[4], const unsigned a[4],
                                         unsigned b0, unsigned b1) {
    asm volatile("mma.sync.aligned.m16n8k16.row.col.f32.f16.f16.f32 "
                 "{%0,%1,%2,%3}, {%4,%5,%6,%7}, {%8,%9}, {%0,%1,%2,%3};"
                 : "+f"(c[0]), "+f"(c[1]), "+f"(c[2]), "+f"(c[3])
                 : "r"(a[0]), "r"(a[1]), "r"(a[2]), "r"(a[3]), "r"(b0), "r"(b1));
}
// fp16 inputs, fp16 accumulate (correction terms; possibly double-rate)
__device__ __forceinline__ void mma16816h(unsigned c[2], const unsigned a[4],
                                          unsigned b0, unsigned b1) {
    asm volatile("mma.sync.aligned.m16n8k16.row.col.f16.f16.f16.f16 "
                 "{%0,%1}, {%2,%3,%4,%5}, {%6,%7}, {%0,%1};"
                 : "+r"(c[0]), "+r"(c[1])
                 : "r"(a[0]), "r"(a[1]), "r"(a[2]), "r"(a[3]), "r"(b0), "r"(b1));
}
__device__ __forceinline__ void merge_corr(float c[4], const unsigned cr[2]) {
    __half2 h0 = *(const __half2*)&cr[0];
    __half2 h1 = *(const __half2*)&cr[1];
    float2 f0 = __half22float2(h0);
    float2 f1 = __half22float2(h1);
    c[0] += f0.x; c[1] += f0.y; c[2] += f1.x; c[3] += f1.y;
}

// ---------------- problem constants ----------------
#define NB    32
#define OH1   56
#define NPIX1 (OH1*OH1)   // 3136
#define N1    (NB*NPIX1)  // 100352
#define K1    243
#define OH2   24
#define P2    (OH2*OH2)   // 576
#define N2    (NB*P2)     // 18432
#define K2    20736
#define MCH   256
#define RR    32
#define DD    8
#define CC    10
#define OO    16

// mma tiling
#define KCH    32
#define NCH2   (K2/KCH)     // 648
#define NCH1   8            // 243 padded to 256
#define OFF_ALO 10240       // bytes; A tile = 128 rows x 80B
#define OFF_BHI 20480
#define OFF_BLO 30720
#define STAGE_B 40960
#define CONV_SMEM (2*STAGE_B)   // 80 KB

// ---------------- scratch (static device memory only) ----------------
__device__ __align__(16) unsigned g_xp[NB*3*64*64];      // x packed (fp16hi | fp16lo<<16)
__device__ __align__(16) unsigned g_h1p[NB*MCH*NPIX1];   // conv1 out packed
__device__ __align__(16) float    g_caps[NB*RR*P2*DD];
__device__ __align__(16) unsigned g_w1img[NCH1*2*256*16]; // conv1 weights image
__device__ __align__(16) unsigned g_w2img[NCH2*2*256*16]; // conv2 weights image
__device__ __align__(16) float    g_WV[NB*RR*CC*DD];
__device__ __align__(16) float    g_G[NB*RR*CC*DD];
__device__ __align__(16) float    g_v[NB*CC*OO];
__device__ __align__(16) float    g_blog[NB*RR*P2*CC];

// ---------------- fp16 split pack ----------------
__device__ __forceinline__ unsigned pack_split(float v) {
    __half h = __float2half_rn(v);
    float hf = __half2float(h);
    __half l = __float2half_rn(v - hf);
    return (unsigned)__half_as_ushort(h) | ((unsigned)__half_as_ushort(l) << 16);
}

// ---------------- input pack ----------------
__global__ void xpack_kernel(const float* __restrict__ x) {
    int idx = blockIdx.x * 256 + threadIdx.x;
    if (idx >= NB*3*64*64) return;
    g_xp[idx] = pack_split(x[idx]);
}

// ---------------- weight split into per-chunk linear images ----------------
__global__ void w1split_kernel(const float* __restrict__ w1) {
    int t  = blockIdx.x * 256 + threadIdx.x;   // 256 ch * 128 k-pairs
    if (t >= 256*128) return;
    int ch = t >> 7;
    int kp = t & 127;
    int k  = 2*kp;
    unsigned p0 = (k   < K1) ? pack_split(w1[ch*K1 + k])     : 0u;
    unsigned p1 = (k+1 < K1) ? pack_split(w1[ch*K1 + k + 1]) : 0u;
    unsigned hi01 = __byte_perm(p0, p1, 0x5410);
    unsigned lo01 = __byte_perm(p0, p1, 0x7632);
    int chunk = k >> 5, kk = k & 31;
    g_w1img[((chunk*2 + 0)*256 + ch)*16 + (kk >> 1)] = hi01;
    g_w1img[((chunk*2 + 1)*256 + ch)*16 + (kk >> 1)] = lo01;
}
__global__ void w2split_kernel(const float* __restrict__ w2) {
    int t  = blockIdx.x * 256 + threadIdx.x;  // 256ch * K2/2 pairs
    int ch = t / (K2/2);
    int kp = t - ch*(K2/2);
    int k  = 2*kp;
    unsigned p0 = pack_split(w2[ch*K2 + k]);
    unsigned p1 = pack_split(w2[ch*K2 + k + 1]);
    unsigned hi01 = __byte_perm(p0, p1, 0x5410);
    unsigned lo01 = __byte_perm(p0, p1, 0x7632);
    int chunk = k >> 5, kk = k & 31;
    g_w2img[((chunk*2 + 0)*256 + ch)*16 + (kk >> 1)] = hi01;
    g_w2img[((chunk*2 + 1)*256 + ch)*16 + (kk >> 1)] = lo01;
}

// ---------------- conv: fp16-split implicit GEMM on mma.sync ----------------
// D[128 spatial][128 ch] per CTA. 8 warps (4m x 2n), warp tile 32x64.
// Main term hi*hi in f32 acc; corrections (lo*hi + hi*lo) in f16 acc,
// merged into the f32 accumulators every j-group (k=16 span -> no accuracy loss).
template<int CONV>
__global__ __launch_bounds__(256, 2)
void conv_mma(const float* __restrict__ bias)
{
    constexpr int NCHT  = (CONV == 1) ? NCH1 : NCH2;
    constexpr int CHSTR = (CONV == 1) ? 4096 : NPIX1;  // input channel stride
    constexpr int IW    = (CONV == 1) ? 64 : OH1;      // input row stride
    const unsigned* img = (CONV == 1) ? g_w1img : g_w2img;
    const unsigned* act = (CONV == 1) ? g_xp   : g_h1p;

    extern __shared__ __align__(128) char smraw[];
    const unsigned sb = smem_u32(smraw);
    const int tid  = threadIdx.x;
    const int lane = tid & 31;
    const int wid  = tid >> 5;
    const int wm   = wid & 3;      // m-warp 0..3 (32 rows each)
    const int wn   = wid >> 2;     // n-warp 0..1 (64 ch each)
    const int m0   = blockIdx.x * 128;
    const int ch0  = blockIdx.y * 128;

    // ---- fill-state: this thread fills k-pair p for rows rbase+16*i ----
    const int p     = tid & 15;
    const int rbase = tid >> 4;
    int ic, ky, kx, kglob;
    { kglob = 2*p; ic = 0; ky = kglob/9; kx = kglob - 9*ky; }
    int naddr[8];
#pragma unroll
    for (int i = 0; i < 8; ++i) {
        int nsp = m0 + rbase + 16*i;
        if (CONV == 1) {
            int b = nsp / NPIX1, pix = nsp - b*NPIX1;
            int oy = pix / OH1, ox = pix - oy*OH1;
            naddr[i] = b*(3*4096) + oy*64 + ox;
        } else {
            int b = nsp / P2, rem = nsp - b*P2;
            int oy = rem / OH2, ox = rem - oy*OH2;
            naddr[i] = b*(MCH*NPIX1) + oy*(2*OH1) + ox*2;
        }
    }

    float acc[2][8][4];
#pragma unroll
    for (int mt = 0; mt < 2; ++mt)
#pragma unroll
        for (int nt = 0; nt < 8; ++nt)
#pragma unroll
            for (int q = 0; q < 4; ++q) acc[mt][nt][q] = 0.f;

    // ldmatrix lane address components
    const int arow = (lane & 7) + ((lane >> 3) & 1)*8;
    const int acol = ((lane >> 4) & 1)*8;
    const int brow = (lane & 7) + ((lane >> 4) & 1)*8;
    const int bcol = ((lane >> 3) & 1)*8;
    const unsigned aoff = (unsigned)((wm*32 + arow)*80 + acol*2);
    const unsigned boff = (unsigned)(OFF_BHI + (wn*64 + brow)*80 + bcol*2);

    unsigned wreg[16];

    // load A(next chunk) pixels into registers; advances k-state
    auto LDG_A = [&]() {
        int ka  = ic*CHSTR + ky*IW + kx;
        int ka2 = ka + ((kx == 8) ? ((ky == 8) ? (CHSTR - 8*IW - 8) : (IW - 8)) : 1);
        if (CONV == 1) {
            const bool v0 = (kglob < K1), v1 = (kglob + 1 < K1);
            const int o0 = v0 ? ka : 0, o1 = v1 ? ka2 : 0;
#pragma unroll
            for (int i = 0; i < 8; ++i) {
                unsigned w0 = act[naddr[i] + o0];
                unsigned w1v = act[naddr[i] + o1];
                wreg[2*i]   = v0 ? w0  : 0u;
                wreg[2*i+1] = v1 ? w1v : 0u;
            }
        } else {
#pragma unroll
            for (int i = 0; i < 8; ++i) {
                wreg[2*i]   = act[naddr[i] + ka];
                wreg[2*i+1] = act[naddr[i] + ka2];
            }
        }
        kglob += 32;
        kx += 5; ky += 3;                 // advance k by 32 (= 3*9 + 5)
        if (kx >= 9) { kx -= 9; ++ky; }
        if (ky >= 9) { ky -= 9; ++ic; }
    };
    // split + store the prefetched A registers into stage st
    auto STS_A = [&](unsigned st) {
#pragma unroll
        for (int i = 0; i < 8; ++i) {
            unsigned hi01 = __byte_perm(wreg[2*i], wreg[2*i+1], 0x5410);
            unsigned lo01 = __byte_perm(wreg[2*i], wreg[2*i+1], 0x7632);
            unsigned d = st + (unsigned)(rbase + 16*i)*80 + 4u*p;
            asm volatile("st.shared.b32 [%0], %1;" :: "r"(d), "r"(hi01) : "memory");
            asm volatile("st.shared.b32 [%0], %1;" :: "r"(d + OFF_ALO), "r"(lo01) : "memory");
        }
    };
    // B weights via cp.async from linear pre-split image
    auto B_FILL = [&](int c, unsigned st) {
#pragma unroll
        for (int it = 0; it < 4; ++it) {
            int g     = tid + 256*it;
            int plane = g >> 9;
            int chrow = (g >> 2) & 127;
            int j     = g & 3;
            const unsigned* src = img + (((c*2 + plane)*256) + ch0 + chrow)*16 + j*4;
            unsigned dst = st + (plane ? OFF_BLO : OFF_BHI) + (unsigned)chrow*80 + j*16;
            cp16(dst, src);
        }
        cp_commit();
    };

    // one kh phase: 12 ldm4; per j: 4 f32-acc mma (main) + 8 f16-acc mma (corr) + merge
    auto MMA_KH = [&](unsigned st, int kh) {
        const unsigned ka_ = st + aoff + kh*32;
        const unsigned kb_ = st + boff + kh*32;
        unsigned ah[2][4], al[2][4], bh[4], bl[4];
        ldm4(ah[0], ka_);
        ldm4(ah[1], ka_ + 1280);
        ldm4(al[0], ka_ + OFF_ALO);
        ldm4(al[1], ka_ + OFF_ALO + 1280);
#pragma unroll
        for (int j = 0; j < 4; ++j) {
            ldm4(bh, kb_ + j*1280);
            ldm4(bl, kb_ + (OFF_BLO - OFF_BHI) + j*1280);
            // main: hi*hi, f32 accumulate
            mma16816(acc[0][2*j],   ah[0], bh[0], bh[1]);
            mma16816(acc[0][2*j+1], ah[0], bh[2], bh[3]);
            mma16816(acc[1][2*j],   ah[1], bh[0], bh[1]);
            mma16816(acc[1][2*j+1], ah[1], bh[2], bh[3]);
            // corrections: lo*hi + hi*lo, f16 accumulate (short span)
            unsigned cr0[2] = {0u, 0u}, cr1[2] = {0u, 0u};
            unsigned cr2[2] = {0u, 0u}, cr3[2] = {0u, 0u};
            mma16816h(cr0, al[0], bh[0], bh[1]); mma16816h(cr0, ah[0], bl[0], bl[1]);
            mma16816h(cr1, al[0], bh[2], bh[3]); mma16816h(cr1, ah[0], bl[2], bl[3]);
            mma16816h(cr2, al[1], bh[0], bh[1]); mma16816h(cr2, ah[1], bl[0], bl[1]);
            mma16816h(cr3, al[1], bh[2], bh[3]); mma16816h(cr3, ah[1], bl[2], bl[3]);
            merge_corr(acc[0][2*j],   cr0);
            merge_corr(acc[0][2*j+1], cr1);
            merge_corr(acc[1][2*j],   cr2);
            merge_corr(acc[1][2*j+1], cr3);
        }
    };

    // prologue: fill stage 0
    LDG_A();
    B_FILL(0, sb);
    STS_A(sb);
    cp_wait<0>();
    __syncthreads();

#pragma unroll 1
    for (int c = 0; c < NCHT; ++c) {
        const unsigned st  = sb + (unsigned)(c & 1)*STAGE_B;
        const unsigned st2 = sb + (unsigned)((c + 1) & 1)*STAGE_B;
        const bool pre = (c + 1 < NCHT);

        if (pre) {
            LDG_A();            // latency covered by the MMA section below
            B_FILL(c + 1, st2);
        }
        MMA_KH(st, 0);
        if (pre) STS_A(st2);    // writes the other buffer; safe pre-sync
        MMA_KH(st, 1);
        cp_wait<0>();           // B(c+1) landed
        __syncthreads();        // stage c free, stage c+1 visible
    }

    // ---- epilogue ----
#pragma unroll
    for (int mt = 0; mt < 2; ++mt) {
        int rowA = m0 + wm*32 + mt*16 + (lane >> 2);
#pragma unroll
        for (int half = 0; half < 2; ++half) {
            int nsp = rowA + half*8;
            if (CONV == 1) {
                int b = nsp / NPIX1, pix = nsp - b*NPIX1;
                size_t obase = (size_t)b*MCH*NPIX1 + pix;
#pragma unroll
                for (int nt = 0; nt < 8; ++nt) {
                    int chb = ch0 + wn*64 + nt*8 + (lane & 3)*2;
#pragma unroll
                    for (int e = 0; e < 2; ++e) {
                        int ch = chb + e;
                        float v = acc[mt][nt][half*2 + e] + bias[ch];
                        v = v > 0.f ? v : 0.f;
                        g_h1p[obase + (size_t)ch*NPIX1] = pack_split(v);
                    }
                }
            } else {
                int b = nsp / P2, pp = nsp - b*P2;
                long obase = ((long)(b*RR))*P2 + pp;
#pragma unroll
                for (int nt = 0; nt < 8; ++nt) {
                    int chb = ch0 + wn*64 + nt*8 + (lane & 3)*2;
#pragma unroll
                    for (int e = 0; e < 2; ++e) {
                        int ch = chb + e;
                        float v = acc[mt][nt][half*2 + e] + bias[ch];
                        int rr = ch >> 3, dd = ch & 7;
                        g_caps[(obase + (long)rr*P2)*DD + dd] = v;
                    }
                }
            }
        }
    }
}

// ---------------- squash primary capsules (in place) ----------------
__global__ void squash_caps_kernel() {
    int v = blockIdx.x * 256 + threadIdx.x;
    if (v >= NB*RR*P2) return;
    float4 lo = *(float4*)&g_caps[v*8];
    float4 hi = *(float4*)&g_caps[v*8 + 4];
    float norm = lo.x*lo.x + lo.y*lo.y + lo.z*lo.z + lo.w*lo.w
               + hi.x*hi.x + hi.y*hi.y + hi.z*hi.z + hi.w*hi.w;
    float scale = norm / ((1.f + norm) * sqrtf(norm + 1e-8f));
    lo.x *= scale; lo.y *= scale; lo.z *= scale; lo.w *= scale;
    hi.x *= scale; hi.y *= scale; hi.z *= scale; hi.w *= scale;
    *(float4*)&g_caps[v*8]     = lo;
    *(float4*)&g_caps[v*8 + 4] = hi;
}

// ---------------- WV[b,r,c,i] = sum_o route_w[r,c,i,o] * v[b,c,o] ----------------
__global__ void wv_kernel(const float* __restrict__ route_w) {
    int idx = blockIdx.x * 128 + threadIdx.x;
    if (idx >= NB*RR*CC*DD) return;
    int b    = idx / (RR*CC*DD);
    int rem  = idx - b*(RR*CC*DD);
    int r    = rem / (CC*DD);
    int rem2 = rem - r*(CC*DD);
    int c    = rem2 / DD;
    int i    = rem2 - c*DD;
    const float* w = route_w + ((r*CC + c)*DD + i)*OO;
    const float* v = g_v + (b*CC + c)*OO;
    float acc = 0.f;
#pragma unroll
    for (int o = 0; o < OO; ++o) acc += w[o] * v[o];
    g_WV[idx] = acc;
}

// ---------------- routing pass ----------------
template<int MODE>
__global__ void pass_kernel() {
    const int b = blockIdx.x, r = blockIdx.y;
    const int tid = threadIdx.x;   // 64 threads
    __shared__ float sWV[CC*DD];
    __shared__ float sG[2][CC*DD];

    if (MODE >= 2) {
        for (int j = tid; j < CC*DD; j += 64)
            sWV[j] = g_WV[(b*RR + r)*CC*DD + j];
    }
    __syncthreads();

    float Gp[CC*DD];
#pragma unroll
    for (int j = 0; j < CC*DD; ++j) Gp[j] = 0.f;

    const float* capbase = g_caps + (size_t)(b*RR + r)*P2*DD;

#pragma unroll 1
    for (int pi = 0; pi < 9; ++pi) {
        int p = pi*64 + tid;
        float4 l0 = *(const float4*)(capbase + p*8);
        float4 l1 = *(const float4*)(capbase + p*8 + 4);
        float cv[8] = { l0.x, l0.y, l0.z, l0.w, l1.x, l1.y, l1.z, l1.w };

        float cw[CC];
        if (MODE == 1) {
#pragma unroll
            for (int c = 0; c < CC; ++c) cw[c] = 0.1f;
        } else {
            float bvv[CC];
            long bidx = ((long)b*RR*P2 + (long)r*P2 + p)*CC;
#pragma unroll
            for (int c = 0; c < CC; ++c) {
                float t = 0.f;
#pragma unroll
                for (int i = 0; i < 8; ++i) t += cv[i] * sWV[c*8 + i];
                bvv[c] = ((MODE == 3) ? g_blog[bidx + c] : 0.f) + t;
                if (MODE == 2) g_blog[bidx + c] = bvv[c];
            }
            float mx = bvv[0];
#pragma unroll
            for (int c = 1; c < CC; ++c) mx = fmaxf(mx, bvv[c]);
            float sum = 0.f;
#pragma unroll
            for (int c = 0; c < CC; ++c) { cw[c] = __expf(bvv[c] - mx); sum += cw[c]; }
            float inv = 1.f / sum;
#pragma unroll
            for (int c = 0; c < CC; ++c) cw[c] *= inv;
        }
#pragma unroll
        for (int c = 0; c < CC; ++c)
#pragma unroll
            for (int i = 0; i < 8; ++i) Gp[c*8 + i] += cw[c] * cv[i];
    }

    int wid2 = tid >> 5, lane = tid & 31;
#pragma unroll
    for (int j = 0; j < CC*DD; ++j) {
        float val = Gp[j];
#pragma unroll
        for (int s = 16; s > 0; s >>= 1) val += __shfl_xor_sync(0xffffffffu, val, s);
        if (lane == 0) sG[wid2][j] = val;
    }
    __syncthreads();
    for (int j = tid; j < CC*DD; j += 64)
        g_G[(b*RR + r)*CC*DD + j] = sG[0][j] + sG[1][j];
}

// ---------------- s = G . W ; v = squash(s) ----------------
__global__ void sv_kernel(const float* __restrict__ route_w, float* __restrict__ dout) {
    const int b = blockIdx.x;
    const int tid = threadIdx.x;     // 160 threads = (c,o)
    __shared__ float sGb[RR*CC*DD];
    __shared__ float ss[CC*OO];

    for (int j = tid; j < RR*CC*DD; j += CC*OO) sGb[j] = g_G[b*RR*CC*DD + j];
    __syncthreads();

    const int c = tid / OO, o = tid - (tid / OO)*OO;
    float s = 0.f;
#pragma unroll 1
    for (int r = 0; r < RR; ++r) {
#pragma unroll
        for (int i = 0; i < DD; ++i)
            s += sGb[(r*CC + c)*DD + i] * route_w[((r*CC + c)*DD + i)*OO + o];
    }
    ss[tid] = s;
    __syncthreads();
    float norm = 0.f;
#pragma unroll
    for (int oo = 0; oo < OO; ++oo) { float t = ss[c*OO + oo]; norm += t*t; }
    float scale = norm / ((1.f + norm) * sqrtf(norm + 1e-8f));
    float val = scale * s;
    g_v[b*CC*OO + tid] = val;
    if (dout) dout[b*CC*OO + tid] = val;
}

// ---------------- launcher ----------------
extern "C" void kernel_launch(void* const* d_in, const int* in_sizes, int n_in,
                              void* d_out, int out_size)
{
    const float* x  = (const float*)d_in[0];   // [32,3,64,64]
    const float* w1 = (const float*)d_in[1];   // [256,3,9,9]
    const float* b1 = (const float*)d_in[2];   // [256]
    const float* w2 = (const float*)d_in[3];   // [256,256,9,9]
    const float* b2 = (const float*)d_in[4];   // [256]
    const float* rw = (const float*)d_in[5];   // [32,10,8,16]
    float* out = (float*)d_out;

    static int smem_set = 0;
    if (!smem_set) {
        cudaFuncSetAttribute(conv_mma<1>,
                             cudaFuncAttributeMaxDynamicSharedMemorySize, CONV_SMEM);
        cudaFuncSetAttribute(conv_mma<2>,
                             cudaFuncAttributeMaxDynamicSharedMemorySize, CONV_SMEM);
        smem_set = 1;
    }

    // input + weight prep
    xpack_kernel<<<(NB*3*64*64 + 255)/256, 256>>>(x);
    w1split_kernel<<<(256*128 + 255)/256, 256>>>(w1);
    w2split_kernel<<<K2/2, 256>>>(w2);

    // conv1 -> g_h1p (mma.sync, relu+bias+pack fused)
    conv_mma<1><<<dim3(N1/128, 2), 256, CONV_SMEM>>>(b1);
    // conv2 -> g_caps (mma.sync)
    conv_mma<2><<<dim3(N2/128, 2), 256, CONV_SMEM>>>(b2);
    // squash primary caps
    squash_caps_kernel<<<(NB*RR*P2 + 255)/256, 256>>>();

    // routing iteration 1
    pass_kernel<1><<<dim3(NB, RR), 64>>>();
    sv_kernel<<<NB, CC*OO>>>(rw, nullptr);
    // routing iteration 2
    wv_kernel<<<(NB*RR*CC*DD + 127)/128, 128>>>(rw);
    pass_kernel<2><<<dim3(NB, RR), 64>>>();
    sv_kernel<<<NB, CC*OO>>>(rw, nullptr);
    // routing iteration 3 (final)
    wv_kernel<<<(NB*RR*CC*DD + 127)/128, 128>>>(rw);
    pass_kernel<3><<<dim3(NB, RR), 64>>>();
    sv_kernel<<<NB, CC*OO>>>(rw, out);
    (void)out_size;
}

// round 16
// speedup vs baseline: 2.2914x; 2.2914x over previous
#include <cuda_runtime.h>
#include <cuda_fp16.h>

typedef unsigned long long u64;

// ---------------- cp.async helpers ----------------
__device__ __forceinline__ unsigned smem_u32(const void* p) {
    return (unsigned)__cvta_generic_to_shared(p);
}
__device__ __forceinline__ void cp16(unsigned dst, const void* src) {
    asm volatile("cp.async.cg.shared.global [%0], [%1], 16;"
                 :: "r"(dst), "l"(src));
}
__device__ __forceinline__ void cp_commit() {
    asm volatile("cp.async.commit_group;");
}
template<int N>
__device__ __forceinline__ void cp_wait() {
    asm volatile("cp.async.wait_group %0;" :: "n"(N));
}

// ---------------- mma.sync helpers (baseline PTX, no 'a' features) ----------------
__device__ __forceinline__ void ldm4(unsigned r[4], unsigned addr) {
    asm volatile("ldmatrix.sync.aligned.m8n8.x4.shared.b16 {%0,%1,%2,%3}, [%4];"
                 : "=r"(r[0]), "=r"(r[1]), "=r"(r[2]), "=r"(r[3]) : "r"(addr));
}
// fp16 inputs, fp32 accumulate
__device__ __forceinline__ void mma16816(float c[4], const unsigned a[4],
                                         unsigned b0, unsigned b1) {
    asm volatile("mma.sync.aligned.m16n8k16.row.col.f32.f16.f16.f32 "
                 "{%0,%1,%2,%3}, {%4,%5,%6,%7}, {%8,%9}, {%0,%1,%2,%3};"
                 : "+f"(c[0]), "+f"(c[1]), "+f"(c[2]), "+f"(c[3])
                 : "r"(a[0]), "r"(a[1]), "r"(a[2]), "r"(a[3]), "r"(b0), "r"(b1));
}

// ---------------- problem constants ----------------
#define NB    32
#define OH1   56
#define NPIX1 (OH1*OH1)   // 3136
#define N1    (NB*NPIX1)  // 100352
#define K1    243
#define OH2   24
#define P2    (OH2*OH2)   // 576
#define N2    (NB*P2)     // 18432
#define K2    20736
#define MCH   256
#define RR    32
#define DD    8
#define CC    10
#define OO    16

// mma tiling
#define KCH    32
#define NCH2   (K2/KCH)     // 648
#define NCH1   8            // 243 padded to 256
#define OFF_ALO 10240       // bytes; A tile = 128 rows x 80B
#define OFF_BHI 20480
#define OFF_BLO 30720
#define STAGE_B 40960
#define CONV_SMEM (2*STAGE_B)   // 80 KB

// ---------------- scratch (static device memory only) ----------------
__device__ __align__(16) unsigned g_xp[NB*3*64*64];      // x packed (fp16hi | fp16lo<<16)
__device__ __align__(16) unsigned g_h1p[NB*MCH*NPIX1];   // conv1 out packed
__device__ __align__(16) float    g_caps[NB*RR*P2*DD];
__device__ __align__(16) unsigned g_w1img[NCH1*2*256*16]; // conv1 weights image (hi+lo planes)
__device__ __align__(16) unsigned g_w2img[NCH2*256*16];   // conv2 weights image (hi plane only)
__device__ __align__(16) float    g_WV[NB*RR*CC*DD];
__device__ __align__(16) float    g_G[NB*RR*CC*DD];
__device__ __align__(16) float    g_v[NB*CC*OO];
__device__ __align__(16) float    g_blog[NB*RR*P2*CC];

// ---------------- fp16 split pack ----------------
__device__ __forceinline__ unsigned pack_split(float v) {
    __half h = __float2half_rn(v);
    float hf = __half2float(h);
    __half l = __float2half_rn(v - hf);
    return (unsigned)__half_as_ushort(h) | ((unsigned)__half_as_ushort(l) << 16);
}

// ---------------- input pack ----------------
__global__ void xpack_kernel(const float* __restrict__ x) {
    int idx = blockIdx.x * 256 + threadIdx.x;
    if (idx >= NB*3*64*64) return;
    g_xp[idx] = pack_split(x[idx]);
}

// ---------------- weight split into per-chunk linear images ----------------
__global__ void w1split_kernel(const float* __restrict__ w1) {
    int t  = blockIdx.x * 256 + threadIdx.x;   // 256 ch * 128 k-pairs
    if (t >= 256*128) return;
    int ch = t >> 7;
    int kp = t & 127;
    int k  = 2*kp;
    unsigned p0 = (k   < K1) ? pack_split(w1[ch*K1 + k])     : 0u;
    unsigned p1 = (k+1 < K1) ? pack_split(w1[ch*K1 + k + 1]) : 0u;
    unsigned hi01 = __byte_perm(p0, p1, 0x5410);
    unsigned lo01 = __byte_perm(p0, p1, 0x7632);
    int chunk = k >> 5, kk = k & 31;
    g_w1img[((chunk*2 + 0)*256 + ch)*16 + (kk >> 1)] = hi01;
    g_w1img[((chunk*2 + 1)*256 + ch)*16 + (kk >> 1)] = lo01;
}
// conv2: hi plane only (1-term path)
__global__ void w2split_kernel(const float* __restrict__ w2) {
    int t  = blockIdx.x * 256 + threadIdx.x;  // 256ch * K2/2 pairs
    int ch = t / (K2/2);
    int kp = t - ch*(K2/2);
    int k  = 2*kp;
    __half h0 = __float2half_rn(w2[ch*K2 + k]);
    __half h1 = __float2half_rn(w2[ch*K2 + k + 1]);
    unsigned hi01 = (unsigned)__half_as_ushort(h0) | ((unsigned)__half_as_ushort(h1) << 16);
    int chunk = k >> 5, kk = k & 31;
    g_w2img[(chunk*256 + ch)*16 + (kk >> 1)] = hi01;
}

// ---------------- conv: fp16 implicit GEMM on mma.sync ----------------
// D[128 spatial][128 ch] per CTA. 8 warps (4m x 2n), warp tile 32x64.
// CONV==1: 3-term fp16-split (hi*hi + hi*lo + lo*hi), f32 acc  -> g_h1p (relu+bias+pack)
// CONV==2: 1-term plain fp16 (hi*hi), f32 acc                  -> g_caps
template<int CONV>
__global__ __launch_bounds__(256, 2)
void conv_mma(const float* __restrict__ bias)
{
    constexpr int NCHT  = (CONV == 1) ? NCH1 : NCH2;
    constexpr int CHSTR = (CONV == 1) ? 4096 : NPIX1;  // input channel stride
    constexpr int IW    = (CONV == 1) ? 64 : OH1;      // input row stride
    const unsigned* img = (CONV == 1) ? g_w1img : g_w2img;
    const unsigned* act = (CONV == 1) ? g_xp   : g_h1p;

    extern __shared__ __align__(128) char smraw[];
    const unsigned sb = smem_u32(smraw);
    const int tid  = threadIdx.x;
    const int lane = tid & 31;
    const int wid  = tid >> 5;
    const int wm   = wid & 3;      // m-warp 0..3 (32 rows each)
    const int wn   = wid >> 2;     // n-warp 0..1 (64 ch each)
    const int m0   = blockIdx.x * 128;
    const int ch0  = blockIdx.y * 128;

    // ---- fill-state: this thread fills k-pair p for rows rbase+16*i ----
    const int p     = tid & 15;
    const int rbase = tid >> 4;
    int ic, ky, kx, kglob;
    { kglob = 2*p; ic = 0; ky = kglob/9; kx = kglob - 9*ky; }
    int naddr[8];
#pragma unroll
    for (int i = 0; i < 8; ++i) {
        int nsp = m0 + rbase + 16*i;
        if (CONV == 1) {
            int b = nsp / NPIX1, pix = nsp - b*NPIX1;
            int oy = pix / OH1, ox = pix - oy*OH1;
            naddr[i] = b*(3*4096) + oy*64 + ox;
        } else {
            int b = nsp / P2, rem = nsp - b*P2;
            int oy = rem / OH2, ox = rem - oy*OH2;
            naddr[i] = b*(MCH*NPIX1) + oy*(2*OH1) + ox*2;
        }
    }

    float acc[2][8][4];
#pragma unroll
    for (int mt = 0; mt < 2; ++mt)
#pragma unroll
        for (int nt = 0; nt < 8; ++nt)
#pragma unroll
            for (int q = 0; q < 4; ++q) acc[mt][nt][q] = 0.f;

    // ldmatrix lane address components
    const int arow = (lane & 7) + ((lane >> 3) & 1)*8;
    const int acol = ((lane >> 4) & 1)*8;
    const int brow = (lane & 7) + ((lane >> 4) & 1)*8;
    const int bcol = ((lane >> 3) & 1)*8;
    const unsigned aoff = (unsigned)((wm*32 + arow)*80 + acol*2);
    const unsigned boff = (unsigned)(OFF_BHI + (wn*64 + brow)*80 + bcol*2);

    unsigned wreg[16];

    // load A(next chunk) pixels into registers; advances k-state
    auto LDG_A = [&]() {
        int ka  = ic*CHSTR + ky*IW + kx;
        int ka2 = ka + ((kx == 8) ? ((ky == 8) ? (CHSTR - 8*IW - 8) : (IW - 8)) : 1);
        if (CONV == 1) {
            const bool v0 = (kglob < K1), v1 = (kglob + 1 < K1);
            const int o0 = v0 ? ka : 0, o1 = v1 ? ka2 : 0;
#pragma unroll
            for (int i = 0; i < 8; ++i) {
                unsigned w0 = act[naddr[i] + o0];
                unsigned w1v = act[naddr[i] + o1];
                wreg[2*i]   = v0 ? w0  : 0u;
                wreg[2*i+1] = v1 ? w1v : 0u;
            }
        } else {
#pragma unroll
            for (int i = 0; i < 8; ++i) {
                wreg[2*i]   = act[naddr[i] + ka];
                wreg[2*i+1] = act[naddr[i] + ka2];
            }
        }
        kglob += 32;
        kx += 5; ky += 3;                 // advance k by 32 (= 3*9 + 5)
        if (kx >= 9) { kx -= 9; ++ky; }
        if (ky >= 9) { ky -= 9; ++ic; }
    };
    // split + store the prefetched A registers into stage st
    auto STS_A = [&](unsigned st) {
#pragma unroll
        for (int i = 0; i < 8; ++i) {
            unsigned hi01 = __byte_perm(wreg[2*i], wreg[2*i+1], 0x5410);
            unsigned d = st + (unsigned)(rbase + 16*i)*80 + 4u*p;
            asm volatile("st.shared.b32 [%0], %1;" :: "r"(d), "r"(hi01) : "memory");
            if (CONV == 1) {
                unsigned lo01 = __byte_perm(wreg[2*i], wreg[2*i+1], 0x7632);
                asm volatile("st.shared.b32 [%0], %1;" :: "r"(d + OFF_ALO), "r"(lo01) : "memory");
            }
        }
    };
    // B weights via cp.async from linear pre-split image
    auto B_FILL = [&](int c, unsigned st) {
        if (CONV == 1) {
#pragma unroll
            for (int it = 0; it < 4; ++it) {
                int g     = tid + 256*it;
                int plane = g >> 9;
                int chrow = (g >> 2) & 127;
                int j     = g & 3;
                const unsigned* src = img + (((c*2 + plane)*256) + ch0 + chrow)*16 + j*4;
                unsigned dst = st + (plane ? OFF_BLO : OFF_BHI) + (unsigned)chrow*80 + j*16;
                cp16(dst, src);
            }
        } else {
#pragma unroll
            for (int it = 0; it < 2; ++it) {
                int g     = tid + 256*it;       // 0..511 = 128 rows x 4 j
                int chrow = (g >> 2) & 127;
                int j     = g & 3;
                const unsigned* src = img + ((c*256) + ch0 + chrow)*16 + j*4;
                unsigned dst = st + OFF_BHI + (unsigned)chrow*80 + j*16;
                cp16(dst, src);
            }
        }
        cp_commit();
    };

    // one kh phase
    auto MMA_KH = [&](unsigned st, int kh) {
        const unsigned ka_ = st + aoff + kh*32;
        const unsigned kb_ = st + boff + kh*32;
        if (CONV == 2) {
            unsigned ah[2][4], bb[4];
            ldm4(ah[0], ka_);
            ldm4(ah[1], ka_ + 1280);
#pragma unroll
            for (int j = 0; j < 4; ++j) {
                ldm4(bb, kb_ + j*1280);
                mma16816(acc[0][2*j],   ah[0], bb[0], bb[1]);
                mma16816(acc[0][2*j+1], ah[0], bb[2], bb[3]);
                mma16816(acc[1][2*j],   ah[1], bb[0], bb[1]);
                mma16816(acc[1][2*j+1], ah[1], bb[2], bb[3]);
            }
        } else {
            unsigned ah[2][4], al[2][4], bb[4];
            ldm4(ah[0], ka_);
            ldm4(ah[1], ka_ + 1280);
            ldm4(al[0], ka_ + OFF_ALO);
            ldm4(al[1], ka_ + OFF_ALO + 1280);
#pragma unroll
            for (int j = 0; j < 4; ++j) {
                ldm4(bb, kb_ + j*1280);
                mma16816(acc[0][2*j],   ah[0], bb[0], bb[1]);
                mma16816(acc[0][2*j+1], ah[0], bb[2], bb[3]);
                mma16816(acc[1][2*j],   ah[1], bb[0], bb[1]);
                mma16816(acc[1][2*j+1], ah[1], bb[2], bb[3]);
                mma16816(acc[0][2*j],   al[0], bb[0], bb[1]);
                mma16816(acc[0][2*j+1], al[0], bb[2], bb[3]);
                mma16816(acc[1][2*j],   al[1], bb[0], bb[1]);
                mma16816(acc[1][2*j+1], al[1], bb[2], bb[3]);
            }
#pragma unroll
            for (int j = 0; j < 4; ++j) {
                ldm4(bb, kb_ + (OFF_BLO - OFF_BHI) + j*1280);
                mma16816(acc[0][2*j],   ah[0], bb[0], bb[1]);
                mma16816(acc[0][2*j+1], ah[0], bb[2], bb[3]);
                mma16816(acc[1][2*j],   ah[1], bb[0], bb[1]);
                mma16816(acc[1][2*j+1], ah[1], bb[2], bb[3]);
            }
        }
    };

    // prologue: fill stage 0
    LDG_A();
    B_FILL(0, sb);
    STS_A(sb);
    cp_wait<0>();
    __syncthreads();

#pragma unroll 1
    for (int c = 0; c < NCHT; ++c) {
        const unsigned st  = sb + (unsigned)(c & 1)*STAGE_B;
        const unsigned st2 = sb + (unsigned)((c + 1) & 1)*STAGE_B;
        const bool pre = (c + 1 < NCHT);

        if (pre) {
            LDG_A();            // latency covered by the MMA section below
            B_FILL(c + 1, st2);
        }
        MMA_KH(st, 0);
        if (pre) STS_A(st2);    // writes the other buffer; safe pre-sync
        MMA_KH(st, 1);
        cp_wait<0>();           // B(c+1) landed
        __syncthreads();        // stage c free, stage c+1 visible
    }

    // ---- epilogue ----
#pragma unroll
    for (int mt = 0; mt < 2; ++mt) {
        int rowA = m0 + wm*32 + mt*16 + (lane >> 2);
#pragma unroll
        for (int half = 0; half < 2; ++half) {
            int nsp = rowA + half*8;
            if (CONV == 1) {
                int b = nsp / NPIX1, pix = nsp - b*NPIX1;
                size_t obase = (size_t)b*MCH*NPIX1 + pix;
#pragma unroll
                for (int nt = 0; nt < 8; ++nt) {
                    int chb = ch0 + wn*64 + nt*8 + (lane & 3)*2;
#pragma unroll
                    for (int e = 0; e < 2; ++e) {
                        int ch = chb + e;
                        float v = acc[mt][nt][half*2 + e] + bias[ch];
                        v = v > 0.f ? v : 0.f;
                        g_h1p[obase + (size_t)ch*NPIX1] = pack_split(v);
                    }
                }
            } else {
                int b = nsp / P2, pp = nsp - b*P2;
                long obase = ((long)(b*RR))*P2 + pp;
#pragma unroll
                for (int nt = 0; nt < 8; ++nt) {
                    int chb = ch0 + wn*64 + nt*8 + (lane & 3)*2;
#pragma unroll
                    for (int e = 0; e < 2; ++e) {
                        int ch = chb + e;
                        float v = acc[mt][nt][half*2 + e] + bias[ch];
                        int rr = ch >> 3, dd = ch & 7;
                        g_caps[(obase + (long)rr*P2)*DD + dd] = v;
                    }
                }
            }
        }
    }
}

// ---------------- squash primary capsules (in place) ----------------
__global__ void squash_caps_kernel() {
    int v = blockIdx.x * 256 + threadIdx.x;
    if (v >= NB*RR*P2) return;
    float4 lo = *(float4*)&g_caps[v*8];
    float4 hi = *(float4*)&g_caps[v*8 + 4];
    float norm = lo.x*lo.x + lo.y*lo.y + lo.z*lo.z + lo.w*lo.w
               + hi.x*hi.x + hi.y*hi.y + hi.z*hi.z + hi.w*hi.w;
    float scale = norm / ((1.f + norm) * sqrtf(norm + 1e-8f));
    lo.x *= scale; lo.y *= scale; lo.z *= scale; lo.w *= scale;
    hi.x *= scale; hi.y *= scale; hi.z *= scale; hi.w *= scale;
    *(float4*)&g_caps[v*8]     = lo;
    *(float4*)&g_caps[v*8 + 4] = hi;
}

// ---------------- WV[b,r,c,i] = sum_o route_w[r,c,i,o] * v[b,c,o] ----------------
__global__ void wv_kernel(const float* __restrict__ route_w) {
    int idx = blockIdx.x * 128 + threadIdx.x;
    if (idx >= NB*RR*CC*DD) return;
    int b    = idx / (RR*CC*DD);
    int rem  = idx - b*(RR*CC*DD);
    int r    = rem / (CC*DD);
    int rem2 = rem - r*(CC*DD);
    int c    = rem2 / DD;
    int i    = rem2 - c*DD;
    const float* w = route_w + ((r*CC + c)*DD + i)*OO;
    const float* v = g_v + (b*CC + c)*OO;
    float acc = 0.f;
#pragma unroll
    for (int o = 0; o < OO; ++o) acc += w[o] * v[o];
    g_WV[idx] = acc;
}

// ---------------- routing pass ----------------
template<int MODE>
__global__ void pass_kernel() {
    const int b = blockIdx.x, r = blockIdx.y;
    const int tid = threadIdx.x;   // 64 threads
    __shared__ float sWV[CC*DD];
    __shared__ float sG[2][CC*DD];

    if (MODE >= 2) {
        for (int j = tid; j < CC*DD; j += 64)
            sWV[j] = g_WV[(b*RR + r)*CC*DD + j];
    }
    __syncthreads();

    float Gp[CC*DD];
#pragma unroll
    for (int j = 0; j < CC*DD; ++j) Gp[j] = 0.f;

    const float* capbase = g_caps + (size_t)(b*RR + r)*P2*DD;

#pragma unroll 1
    for (int pi = 0; pi < 9; ++pi) {
        int p = pi*64 + tid;
        float4 l0 = *(const float4*)(capbase + p*8);
        float4 l1 = *(const float4*)(capbase + p*8 + 4);
        float cv[8] = { l0.x, l0.y, l0.z, l0.w, l1.x, l1.y, l1.z, l1.w };

        float cw[CC];
        if (MODE == 1) {
#pragma unroll
            for (int c = 0; c < CC; ++c) cw[c] = 0.1f;
        } else {
            float bvv[CC];
            long bidx = ((long)b*RR*P2 + (long)r*P2 + p)*CC;
#pragma unroll
            for (int c = 0; c < CC; ++c) {
                float t = 0.f;
#pragma unroll
                for (int i = 0; i < 8; ++i) t += cv[i] * sWV[c*8 + i];
                bvv[c] = ((MODE == 3) ? g_blog[bidx + c] : 0.f) + t;
                if (MODE == 2) g_blog[bidx + c] = bvv[c];
            }
            float mx = bvv[0];
#pragma unroll
            for (int c = 1; c < CC; ++c) mx = fmaxf(mx, bvv[c]);
            float sum = 0.f;
#pragma unroll
            for (int c = 0; c < CC; ++c) { cw[c] = __expf(bvv[c] - mx); sum += cw[c]; }
            float inv = 1.f / sum;
#pragma unroll
            for (int c = 0; c < CC; ++c) cw[c] *= inv;
        }
#pragma unroll
        for (int c = 0; c < CC; ++c)
#pragma unroll
            for (int i = 0; i < 8; ++i) Gp[c*8 + i] += cw[c] * cv[i];
    }

    int wid2 = tid >> 5, lane = tid & 31;
#pragma unroll
    for (int j = 0; j < CC*DD; ++j) {
        float val = Gp[j];
#pragma unroll
        for (int s = 16; s > 0; s >>= 1) val += __shfl_xor_sync(0xffffffffu, val, s);
        if (lane == 0) sG[wid2][j] = val;
    }
    __syncthreads();
    for (int j = tid; j < CC*DD; j += 64)
        g_G[(b*RR + r)*CC*DD + j] = sG[0][j] + sG[1][j];
}

// ---------------- s = G . W ; v = squash(s) ----------------
__global__ void sv_kernel(const float* __restrict__ route_w, float* __restrict__ dout) {
    const int b = blockIdx.x;
    const int tid = threadIdx.x;     // 160 threads = (c,o)
    __shared__ float sGb[RR*CC*DD];
    __shared__ float ss[CC*OO];

    for (int j = tid; j < RR*CC*DD; j += CC*OO) sGb[j] = g_G[b*RR*CC*DD + j];
    __syncthreads();

    const int c = tid / OO, o = tid - (tid / OO)*OO;
    float s = 0.f;
#pragma unroll 1
    for (int r = 0; r < RR; ++r) {
#pragma unroll
        for (int i = 0; i < DD; ++i)
            s += sGb[(r*CC + c)*DD + i] * route_w[((r*CC + c)*DD + i)*OO + o];
    }
    ss[tid] = s;
    __syncthreads();
    float norm = 0.f;
#pragma unroll
    for (int oo = 0; oo < OO; ++oo) { float t = ss[c*OO + oo]; norm += t*t; }
    float scale = norm / ((1.f + norm) * sqrtf(norm + 1e-8f));
    float val = scale * s;
    g_v[b*CC*OO + tid] = val;
    if (dout) dout[b*CC*OO + tid] = val;
}

// ---------------- launcher ----------------
extern "C" void kernel_launch(void* const* d_in, const int* in_sizes, int n_in,
                              void* d_out, int out_size)
{
    const float* x  = (const float*)d_in[0];   // [32,3,64,64]
    const float* w1 = (const float*)d_in[1];   // [256,3,9,9]
    const float* b1 = (const float*)d_in[2];   // [256]
    const float* w2 = (const float*)d_in[3];   // [256,256,9,9]
    const float* b2 = (const float*)d_in[4];   // [256]
    const float* rw = (const float*)d_in[5];   // [32,10,8,16]
    float* out = (float*)d_out;

    static int smem_set = 0;
    if (!smem_set) {
        cudaFuncSetAttribute(conv_mma<1>,
                             cudaFuncAttributeMaxDynamicSharedMemorySize, CONV_SMEM);
        cudaFuncSetAttribute(conv_mma<2>,
                             cudaFuncAttributeMaxDynamicSharedMemorySize, CONV_SMEM);
        smem_set = 1;
    }

    // input + weight prep
    xpack_kernel<<<(NB*3*64*64 + 255)/256, 256>>>(x);
    w1split_kernel<<<(256*128 + 255)/256, 256>>>(w1);
    w2split_kernel<<<K2/2, 256>>>(w2);

    // conv1 -> g_h1p (3-term fp16 split, relu+bias+pack fused)
    conv_mma<1><<<dim3(N1/128, 2), 256, CONV_SMEM>>>(b1);
    // conv2 -> g_caps (1-term plain fp16)
    conv_mma<2><<<dim3(N2/128, 2), 256, CONV_SMEM>>>(b2);
    // squash primary caps
    squash_caps_kernel<<<(NB*RR*P2 + 255)/256, 256>>>();

    // routing iteration 1
    pass_kernel<1><<<dim3(NB, RR), 64>>>();
    sv_kernel<<<NB, CC*OO>>>(rw, nullptr);
    // routing iteration 2
    wv_kernel<<<(NB*RR*CC*DD + 127)/128, 128>>>(rw);
    pass_kernel<2><<<dim3(NB, RR), 64>>>();
    sv_kernel<<<NB, CC*OO>>>(rw, nullptr);
    // routing iteration 3 (final)
    wv_kernel<<<(NB*RR*CC*DD + 127)/128, 128>>>(rw);
    pass_kernel<3><<<dim3(NB, RR), 64>>>();
    sv_kernel<<<NB, CC*OO>>>(rw, out);
    (void)out_size;
}

// round 17
// speedup vs baseline: 2.7897x; 1.2175x over previous
#include <cuda_runtime.h>
#include <cuda_fp16.h>

typedef unsigned long long u64;

// ---------------- cp.async helpers ----------------
__device__ __forceinline__ unsigned smem_u32(const void* p) {
    return (unsigned)__cvta_generic_to_shared(p);
}
__device__ __forceinline__ void cp16(unsigned dst, const void* src) {
    asm volatile("cp.async.cg.shared.global [%0], [%1], 16;"
                 :: "r"(dst), "l"(src));
}
__device__ __forceinline__ void cp_commit() {
    asm volatile("cp.async.commit_group;");
}
template<int N>
__device__ __forceinline__ void cp_wait() {
    asm volatile("cp.async.wait_group %0;" :: "n"(N));
}

// ---------------- mma.sync helpers (baseline PTX, no 'a' features) ----------------
__device__ __forceinline__ void ldm4(unsigned r[4], unsigned addr) {
    asm volatile("ldmatrix.sync.aligned.m8n8.x4.shared.b16 {%0,%1,%2,%3}, [%4];"
                 : "=r"(r[0]), "=r"(r[1]), "=r"(r[2]), "=r"(r[3]) : "r"(addr));
}
// fp16 inputs, fp32 accumulate
__device__ __forceinline__ void mma16816(float c[4], const unsigned a[4],
                                         unsigned b0, unsigned b1) {
    asm volatile("mma.sync.aligned.m16n8k16.row.col.f32.f16.f16.f32 "
                 "{%0,%1,%2,%3}, {%4,%5,%6,%7}, {%8,%9}, {%0,%1,%2,%3};"
                 : "+f"(c[0]), "+f"(c[1]), "+f"(c[2]), "+f"(c[3])
                 : "r"(a[0]), "r"(a[1]), "r"(a[2]), "r"(a[3]), "r"(b0), "r"(b1));
}

// ---------------- problem constants ----------------
#define NB    32
#define OH1   56
#define NPIX1 (OH1*OH1)   // 3136
#define N1    (NB*NPIX1)  // 100352
#define K1    243
#define OH2   24
#define P2    (OH2*OH2)   // 576
#define N2    (NB*P2)     // 18432
#define K2    20736
#define MCH   256
#define RR    32
#define DD    8
#define CC    10
#define OO    16

// mma tiling (1-term fp16, compact 4-stage layout)
#define KCH    32
#define NCH2   (K2/KCH)     // 648
#define NCH1   8            // 243 padded to 256
#define OFF_B  10240        // bytes; A tile = 128 rows x 80B, then B tile 128 x 80B
#define STAGE_SZ 20480
#define CONV_SMEM (4*STAGE_SZ)   // 80 KB

// ---------------- scratch (static device memory only) ----------------
__device__ __align__(16) unsigned g_xp[NB*3*64*64];      // x, fp16 in low 16 bits
__device__ __align__(16) unsigned g_h1p[NB*MCH*NPIX1];   // conv1 out, fp16 in low 16 bits
__device__ __align__(16) float    g_caps[NB*RR*P2*DD];
__device__ __align__(16) unsigned g_w1img[NCH1*256*16];  // conv1 weights image (fp16 pairs)
__device__ __align__(16) unsigned g_w2img[NCH2*256*16];  // conv2 weights image (fp16 pairs)
__device__ __align__(16) float    g_WV[NB*RR*CC*DD];
__device__ __align__(16) float    g_G[NB*RR*CC*DD];
__device__ __align__(16) float    g_v[NB*CC*OO];
__device__ __align__(16) float    g_blog[NB*RR*P2*CC];

// ---------------- input pack (fp16 in low 16 bits) ----------------
__global__ void xpack_kernel(const float* __restrict__ x) {
    int idx = blockIdx.x * 256 + threadIdx.x;
    if (idx >= NB*3*64*64) return;
    g_xp[idx] = (unsigned)__half_as_ushort(__float2half_rn(x[idx]));
}

// ---------------- weight images (fp16 pairs, k-major in 16B groups) ----------------
__global__ void w1split_kernel(const float* __restrict__ w1) {
    int t  = blockIdx.x * 256 + threadIdx.x;   // 256 ch * 128 k-pairs
    if (t >= 256*128) return;
    int ch = t >> 7;
    int kp = t & 127;
    int k  = 2*kp;
    __half h0 = __float2half_rn((k   < K1) ? w1[ch*K1 + k]     : 0.f);
    __half h1 = __float2half_rn((k+1 < K1) ? w1[ch*K1 + k + 1] : 0.f);
    unsigned hi01 = (unsigned)__half_as_ushort(h0) | ((unsigned)__half_as_ushort(h1) << 16);
    int chunk = k >> 5, kk = k & 31;
    g_w1img[(chunk*256 + ch)*16 + (kk >> 1)] = hi01;
}
__global__ void w2split_kernel(const float* __restrict__ w2) {
    int t  = blockIdx.x * 256 + threadIdx.x;  // 256ch * K2/2 pairs
    int ch = t / (K2/2);
    int kp = t - ch*(K2/2);
    int k  = 2*kp;
    __half h0 = __float2half_rn(w2[ch*K2 + k]);
    __half h1 = __float2half_rn(w2[ch*K2 + k + 1]);
    unsigned hi01 = (unsigned)__half_as_ushort(h0) | ((unsigned)__half_as_ushort(h1) << 16);
    int chunk = k >> 5, kk = k & 31;
    g_w2img[(chunk*256 + ch)*16 + (kk >> 1)] = hi01;
}

// ---------------- conv: 1-term fp16 implicit GEMM on mma.sync ----------------
// D[128 spatial][128 ch] per CTA. 8 warps (4m x 2n), warp tile 32x64.
// 4 SMEM stages, TWO chunks per __syncthreads (halved barrier overhead).
template<int CONV>
__global__ __launch_bounds__(256, 2)
void conv_mma(const float* __restrict__ bias)
{
    constexpr int NCHT  = (CONV == 1) ? NCH1 : NCH2;
    constexpr int CHSTR = (CONV == 1) ? 4096 : NPIX1;  // input channel stride
    constexpr int IW    = (CONV == 1) ? 64 : OH1;      // input row stride
    const unsigned* img = (CONV == 1) ? g_w1img : g_w2img;
    const unsigned* act = (CONV == 1) ? g_xp   : g_h1p;

    extern __shared__ __align__(128) char smraw[];
    const unsigned sb = smem_u32(smraw);
    const int tid  = threadIdx.x;
    const int lane = tid & 31;
    const int wid  = tid >> 5;
    const int wm   = wid & 3;      // m-warp 0..3 (32 rows each)
    const int wn   = wid >> 2;     // n-warp 0..1 (64 ch each)
    const int m0   = blockIdx.x * 128;
    const int ch0  = blockIdx.y * 128;

    // ---- fill-state: this thread fills k-pair p for rows rbase+16*i ----
    const int p     = tid & 15;
    const int rbase = tid >> 4;
    int ic, ky, kx, kglob;
    { kglob = 2*p; ic = 0; ky = kglob/9; kx = kglob - 9*ky; }
    int naddr[8];
#pragma unroll
    for (int i = 0; i < 8; ++i) {
        int nsp = m0 + rbase + 16*i;
        if (CONV == 1) {
            int b = nsp / NPIX1, pix = nsp - b*NPIX1;
            int oy = pix / OH1, ox = pix - oy*OH1;
            naddr[i] = b*(3*4096) + oy*64 + ox;
        } else {
            int b = nsp / P2, rem = nsp - b*P2;
            int oy = rem / OH2, ox = rem - oy*OH2;
            naddr[i] = b*(MCH*NPIX1) + oy*(2*OH1) + ox*2;
        }
    }

    float acc[2][8][4];
#pragma unroll
    for (int mt = 0; mt < 2; ++mt)
#pragma unroll
        for (int nt = 0; nt < 8; ++nt)
#pragma unroll
            for (int q = 0; q < 4; ++q) acc[mt][nt][q] = 0.f;

    // ldmatrix lane address components
    const int arow = (lane & 7) + ((lane >> 3) & 1)*8;
    const int acol = ((lane >> 4) & 1)*8;
    const int brow = (lane & 7) + ((lane >> 4) & 1)*8;
    const int bcol = ((lane >> 3) & 1)*8;
    const unsigned aoff = (unsigned)((wm*32 + arow)*80 + acol*2);
    const unsigned boff = (unsigned)(OFF_B + (wn*64 + brow)*80 + bcol*2);

    unsigned wreg[16];

    // load A(next chunk) pixels into registers; advances k-state
    auto LDG_A = [&]() {
        int ka  = ic*CHSTR + ky*IW + kx;
        int ka2 = ka + ((kx == 8) ? ((ky == 8) ? (CHSTR - 8*IW - 8) : (IW - 8)) : 1);
        if (CONV == 1) {
            const bool v0 = (kglob < K1), v1 = (kglob + 1 < K1);
            const int o0 = v0 ? ka : 0, o1 = v1 ? ka2 : 0;
#pragma unroll
            for (int i = 0; i < 8; ++i) {
                unsigned w0 = act[naddr[i] + o0];
                unsigned w1v = act[naddr[i] + o1];
                wreg[2*i]   = v0 ? w0  : 0u;
                wreg[2*i+1] = v1 ? w1v : 0u;
            }
        } else {
#pragma unroll
            for (int i = 0; i < 8; ++i) {
                wreg[2*i]   = act[naddr[i] + ka];
                wreg[2*i+1] = act[naddr[i] + ka2];
            }
        }
        kglob += 32;
        kx += 5; ky += 3;                 // advance k by 32 (= 3*9 + 5)
        if (kx >= 9) { kx -= 9; ++ky; }
        if (ky >= 9) { ky -= 9; ++ic; }
    };
    // pack fp16 pair + store prefetched A registers into stage st
    auto STS_A = [&](unsigned st) {
#pragma unroll
        for (int i = 0; i < 8; ++i) {
            unsigned hi01 = __byte_perm(wreg[2*i], wreg[2*i+1], 0x5410);
            unsigned d = st + (unsigned)(rbase + 16*i)*80 + 4u*p;
            asm volatile("st.shared.b32 [%0], %1;" :: "r"(d), "r"(hi01) : "memory");
        }
    };
    // B weights via cp.async from linear image
    auto B_FILL = [&](int c, unsigned st) {
#pragma unroll
        for (int it = 0; it < 2; ++it) {
            int g     = tid + 256*it;       // 0..511 = 128 rows x 4 j
            int chrow = (g >> 2) & 127;
            int j     = g & 3;
            const unsigned* src = img + ((c*256) + ch0 + chrow)*16 + j*4;
            unsigned dst = st + OFF_B + (unsigned)chrow*80 + j*16;
            cp16(dst, src);
        }
        cp_commit();
    };

    // one kh phase: 6 ldm4 + 16 mma
    auto MMA_KH = [&](unsigned st, int kh) {
        const unsigned ka_ = st + aoff + kh*32;
        const unsigned kb_ = st + boff + kh*32;
        unsigned ah[2][4], bb[4];
        ldm4(ah[0], ka_);
        ldm4(ah[1], ka_ + 1280);
#pragma unroll
        for (int j = 0; j < 4; ++j) {
            ldm4(bb, kb_ + j*1280);
            mma16816(acc[0][2*j],   ah[0], bb[0], bb[1]);
            mma16816(acc[0][2*j+1], ah[0], bb[2], bb[3]);
            mma16816(acc[1][2*j],   ah[1], bb[0], bb[1]);
            mma16816(acc[1][2*j+1], ah[1], bb[2], bb[3]);
        }
    };

    // ---- prologue: fill stages 0 and 1 (chunks 0, 1) ----
    LDG_A();
    B_FILL(0, sb);
    STS_A(sb);
    LDG_A();
    B_FILL(1, sb + STAGE_SZ);
    STS_A(sb + STAGE_SZ);
    cp_wait<0>();
    __syncthreads();

#pragma unroll 1
    for (int c = 0; c < NCHT; c += 2) {
        const unsigned st0 = sb + (unsigned)(c & 3)*STAGE_SZ;
        const unsigned st1 = sb + (unsigned)((c + 1) & 3)*STAGE_SZ;
        const unsigned st2 = sb + (unsigned)((c + 2) & 3)*STAGE_SZ;
        const unsigned st3 = sb + (unsigned)((c + 3) & 3)*STAGE_SZ;
        const bool pre2 = (c + 2 < NCHT);
        const bool pre3 = (c + 3 < NCHT);

        if (pre2) {
            LDG_A();             // chunk c+2 activations
            B_FILL(c + 2, st2);
        }
        MMA_KH(st0, 0);
        MMA_KH(st0, 1);
        if (pre2) STS_A(st2);
        if (pre3) {
            LDG_A();             // chunk c+3 activations
            B_FILL(c + 3, st3);
        }
        MMA_KH(st1, 0);
        MMA_KH(st1, 1);
        if (pre3) STS_A(st3);
        cp_wait<0>();            // B(c+2), B(c+3) landed
        __syncthreads();         // stages c,c+1 free; c+2,c+3 visible
    }

    // ---- epilogue ----
#pragma unroll
    for (int mt = 0; mt < 2; ++mt) {
        int rowA = m0 + wm*32 + mt*16 + (lane >> 2);
#pragma unroll
        for (int half = 0; half < 2; ++half) {
            int nsp = rowA + half*8;
            if (CONV == 1) {
                int b = nsp / NPIX1, pix = nsp - b*NPIX1;
                size_t obase = (size_t)b*MCH*NPIX1 + pix;
#pragma unroll
                for (int nt = 0; nt < 8; ++nt) {
                    int chb = ch0 + wn*64 + nt*8 + (lane & 3)*2;
#pragma unroll
                    for (int e = 0; e < 2; ++e) {
                        int ch = chb + e;
                        float v = acc[mt][nt][half*2 + e] + bias[ch];
                        v = v > 0.f ? v : 0.f;
                        g_h1p[obase + (size_t)ch*NPIX1] =
                            (unsigned)__half_as_ushort(__float2half_rn(v));
                    }
                }
            } else {
                int b = nsp / P2, pp = nsp - b*P2;
                long obase = ((long)(b*RR))*P2 + pp;
#pragma unroll
                for (int nt = 0; nt < 8; ++nt) {
                    int chb = ch0 + wn*64 + nt*8 + (lane & 3)*2;
#pragma unroll
                    for (int e = 0; e < 2; ++e) {
                        int ch = chb + e;
                        float v = acc[mt][nt][half*2 + e] + bias[ch];
                        int rr = ch >> 3, dd = ch & 7;
                        g_caps[(obase + (long)rr*P2)*DD + dd] = v;
                    }
                }
            }
        }
    }
}

// ---------------- squash primary capsules (in place) ----------------
__global__ void squash_caps_kernel() {
    int v = blockIdx.x * 256 + threadIdx.x;
    if (v >= NB*RR*P2) return;
    float4 lo = *(float4*)&g_caps[v*8];
    float4 hi = *(float4*)&g_caps[v*8 + 4];
    float norm = lo.x*lo.x + lo.y*lo.y + lo.z*lo.z + lo.w*lo.w
               + hi.x*hi.x + hi.y*hi.y + hi.z*hi.z + hi.w*hi.w;
    float scale = norm / ((1.f + norm) * sqrtf(norm + 1e-8f));
    lo.x *= scale; lo.y *= scale; lo.z *= scale; lo.w *= scale;
    hi.x *= scale; hi.y *= scale; hi.z *= scale; hi.w *= scale;
    *(float4*)&g_caps[v*8]     = lo;
    *(float4*)&g_caps[v*8 + 4] = hi;
}

// ---------------- WV[b,r,c,i] = sum_o route_w[r,c,i,o] * v[b,c,o] ----------------
__global__ void wv_kernel(const float* __restrict__ route_w) {
    int idx = blockIdx.x * 128 + threadIdx.x;
    if (idx >= NB*RR*CC*DD) return;
    int b    = idx / (RR*CC*DD);
    int rem  = idx - b*(RR*CC*DD);
    int r    = rem / (CC*DD);
    int rem2 = rem - r*(CC*DD);
    int c    = rem2 / DD;
    int i    = rem2 - c*DD;
    const float* w = route_w + ((r*CC + c)*DD + i)*OO;
    const float* v = g_v + (b*CC + c)*OO;
    float acc = 0.f;
#pragma unroll
    for (int o = 0; o < OO; ++o) acc += w[o] * v[o];
    g_WV[idx] = acc;
}

// ---------------- routing pass ----------------
template<int MODE>
__global__ void pass_kernel() {
    const int b = blockIdx.x, r = blockIdx.y;
    const int tid = threadIdx.x;   // 64 threads
    __shared__ float sWV[CC*DD];
    __shared__ float sG[2][CC*DD];

    if (MODE >= 2) {
        for (int j = tid; j < CC*DD; j += 64)
            sWV[j] = g_WV[(b*RR + r)*CC*DD + j];
    }
    __syncthreads();

    float Gp[CC*DD];
#pragma unroll
    for (int j = 0; j < CC*DD; ++j) Gp[j] = 0.f;

    const float* capbase = g_caps + (size_t)(b*RR + r)*P2*DD;

#pragma unroll 1
    for (int pi = 0; pi < 9; ++pi) {
        int p = pi*64 + tid;
        float4 l0 = *(const float4*)(capbase + p*8);
        float4 l1 = *(const float4*)(capbase + p*8 + 4);
        float cv[8] = { l0.x, l0.y, l0.z, l0.w, l1.x, l1.y, l1.z, l1.w };

        float cw[CC];
        if (MODE == 1) {
#pragma unroll
            for (int c = 0; c < CC; ++c) cw[c] = 0.1f;
        } else {
            float bvv[CC];
            long bidx = ((long)b*RR*P2 + (long)r*P2 + p)*CC;
#pragma unroll
            for (int c = 0; c < CC; ++c) {
                float t = 0.f;
#pragma unroll
                for (int i = 0; i < 8; ++i) t += cv[i] * sWV[c*8 + i];
                bvv[c] = ((MODE == 3) ? g_blog[bidx + c] : 0.f) + t;
                if (MODE == 2) g_blog[bidx + c] = bvv[c];
            }
            float mx = bvv[0];
#pragma unroll
            for (int c = 1; c < CC; ++c) mx = fmaxf(mx, bvv[c]);
            float sum = 0.f;
#pragma unroll
            for (int c = 0; c < CC; ++c) { cw[c] = __expf(bvv[c] - mx); sum += cw[c]; }
            float inv = 1.f / sum;
#pragma unroll
            for (int c = 0; c < CC; ++c) cw[c] *= inv;
        }
#pragma unroll
        for (int c = 0; c < CC; ++c)
#pragma unroll
            for (int i = 0; i < 8; ++i) Gp[c*8 + i] += cw[c] * cv[i];
    }

    int wid2 = tid >> 5, lane = tid & 31;
#pragma unroll
    for (int j = 0; j < CC*DD; ++j) {
        float val = Gp[j];
#pragma unroll
        for (int s = 16; s > 0; s >>= 1) val += __shfl_xor_sync(0xffffffffu, val, s);
        if (lane == 0) sG[wid2][j] = val;
    }
    __syncthreads();
    for (int j = tid; j < CC*DD; j += 64)
        g_G[(b*RR + r)*CC*DD + j] = sG[0][j] + sG[1][j];
}

// ---------------- s = G . W ; v = squash(s) ----------------
__global__ void sv_kernel(const float* __restrict__ route_w, float* __restrict__ dout) {
    const int b = blockIdx.x;
    const int tid = threadIdx.x;     // 160 threads = (c,o)
    __shared__ float sGb[RR*CC*DD];
    __shared__ float ss[CC*OO];

    for (int j = tid; j < RR*CC*DD; j += CC*OO) sGb[j] = g_G[b*RR*CC*DD + j];
    __syncthreads();

    const int c = tid / OO, o = tid - (tid / OO)*OO;
    float s = 0.f;
#pragma unroll 1
    for (int r = 0; r < RR; ++r) {
#pragma unroll
        for (int i = 0; i < DD; ++i)
            s += sGb[(r*CC + c)*DD + i] * route_w[((r*CC + c)*DD + i)*OO + o];
    }
    ss[tid] = s;
    __syncthreads();
    float norm = 0.f;
#pragma unroll
    for (int oo = 0; oo < OO; ++oo) { float t = ss[c*OO + oo]; norm += t*t; }
    float scale = norm / ((1.f + norm) * sqrtf(norm + 1e-8f));
    float val = scale * s;
    g_v[b*CC*OO + tid] = val;
    if (dout) dout[b*CC*OO + tid] = val;
}

// ---------------- launcher ----------------
extern "C" void kernel_launch(void* const* d_in, const int* in_sizes, int n_in,
                              void* d_out, int out_size)
{
    const float* x  = (const float*)d_in[0];   // [32,3,64,64]
    const float* w1 = (const float*)d_in[1];   // [256,3,9,9]
    const float* b1 = (const float*)d_in[2];   // [256]
    const float* w2 = (const float*)d_in[3];   // [256,256,9,9]
    const float* b2 = (const float*)d_in[4];   // [256]
    const float* rw = (const float*)d_in[5];   // [32,10,8,16]
    float* out = (float*)d_out;

    static int smem_set = 0;
    if (!smem_set) {
        cudaFuncSetAttribute(conv_mma<1>,
                             cudaFuncAttributeMaxDynamicSharedMemorySize, CONV_SMEM);
        cudaFuncSetAttribute(conv_mma<2>,
                             cudaFuncAttributeMaxDynamicSharedMemorySize, CONV_SMEM);
        smem_set = 1;
    }

    // input + weight prep
    xpack_kernel<<<(NB*3*64*64 + 255)/256, 256>>>(x);
    w1split_kernel<<<(256*128 + 255)/256, 256>>>(w1);
    w2split_kernel<<<K2/2, 256>>>(w2);

    // conv1 -> g_h1p (1-term fp16, relu+bias fused)
    conv_mma<1><<<dim3(N1/128, 2), 256, CONV_SMEM>>>(b1);
    // conv2 -> g_caps (1-term fp16)
    conv_mma<2><<<dim3(N2/128, 2), 256, CONV_SMEM>>>(b2);
    // squash primary caps
    squash_caps_kernel<<<(NB*RR*P2 + 255)/256, 256>>>();

    // routing iteration 1
    pass_kernel<1><<<dim3(NB, RR), 64>>>();
    sv_kernel<<<NB, CC*OO>>>(rw, nullptr);
    // routing iteration 2
    wv_kernel<<<(NB*RR*CC*DD + 127)/128, 128>>>(rw);
    pass_kernel<2><<<dim3(NB, RR), 64>>>();
    sv_kernel<<<NB, CC*OO>>>(rw, nullptr);
    // routing iteration 3 (final)
    wv_kernel<<<(NB*RR*CC*DD + 127)/128, 128>>>(rw);
    pass_kernel<3><<<dim3(NB, RR), 64>>>();
    sv_kernel<<<NB, CC*OO>>>(rw, out);
    (void)out_size;
}